// round 4
// baseline (speedup 1.0000x reference)
#include <cuda_runtime.h>
#include <cuda_bf16.h>
#include <math.h>
#include <cstdint>

#define S_LEN 4096
#define HID   2048
#define NH    8
#define HD    256

// ------------------------- device scratch (no allocs allowed) ---------------
__device__ float    g_Q  [(size_t)S_LEN * HID];          // fp32 proj out
__device__ float    g_K  [(size_t)S_LEN * HD];
__device__ float    g_V  [(size_t)S_LEN * HD];
__device__ float    g_S  [(size_t)NH * S_LEN * S_LEN];   // fp32 scores -> packed P in place
__device__ float    g_A  [(size_t)S_LEN * HID];          // fp32 attn out
__device__ uint32_t g_Xp [(size_t)S_LEN * HID];          // packed bf16 hi/lo operands
__device__ uint32_t g_Qp [(size_t)S_LEN * HID];
__device__ uint32_t g_Kp [(size_t)S_LEN * HD];
__device__ uint32_t g_VTp[(size_t)HD * S_LEN];
__device__ uint32_t g_Ap [(size_t)S_LEN * HID];
__device__ uint32_t g_WqTp[(size_t)HID * HID];
__device__ uint32_t g_WkTp[(size_t)HD * HID];
__device__ uint32_t g_WvTp[(size_t)HD * HID];
__device__ uint32_t g_WoTp[(size_t)HID * HID];

// ------------------------- helpers ------------------------------------------
__device__ __forceinline__ uint32_t pack_bf(float x) {
    __nv_bfloat16 h = __float2bfloat16(x);
    float hf = __bfloat162float(h);
    __nv_bfloat16 l = __float2bfloat16(x - hf);
    return ((uint32_t)__bfloat16_as_ushort(h) << 16) | (uint32_t)__bfloat16_as_ushort(l);
}
__device__ __forceinline__ uint32_t smem_u32(const void* p) {
    uint32_t a;
    asm("{ .reg .u64 t; cvta.to.shared.u64 t, %1; cvt.u32.u64 %0, t; }"
        : "=r"(a) : "l"(p));
    return a;
}
__device__ __forceinline__ void cpa16(uint32_t dst, const void* src) {
    asm volatile("cp.async.cg.shared.global [%0], [%1], 16;"
                 :: "r"(dst), "l"(src));
}
__device__ __forceinline__ void cpa_commit() {
    asm volatile("cp.async.commit_group;");
}

#define MMA_BF16(acc, a, b)                                                     \
    asm volatile(                                                               \
        "mma.sync.aligned.m16n8k16.row.col.f32.bf16.bf16.f32 "                  \
        "{%0,%1,%2,%3},{%4,%5,%6,%7},{%8,%9},{%0,%1,%2,%3};"                    \
        : "+f"((acc)[0]), "+f"((acc)[1]), "+f"((acc)[2]), "+f"((acc)[3])        \
        : "r"((a)[0]), "r"((a)[1]), "r"((a)[2]), "r"((a)[3]),                   \
          "r"((b)[0]), "r"((b)[1]))

// ---------------------------------------------------------------------------
// bf16-split tensor GEMM (NT): C[m,n] = alpha * sum_k A[m,k]*B[n,k]
// A,B are packed hi/lo bf16 words. CTA tile 128x128, K-chunk 32, 256 threads,
// 3-stage cp.async pipeline. M,N mult of 128; K mult of 32 and >= 96.
// SMEM rows padded to 40 words (conflict-free LDS.64 fragment pattern).
// ---------------------------------------------------------------------------
#define TLW 40
#define TILE_WORDS (128 * TLW)          // 5120
#define STAGE_WORDS (2 * TILE_WORDS)    // 10240
#define NSTAGE 3
#define GEMM_SMEM (NSTAGE * STAGE_WORDS * 4)   // 122880 B

__global__ void __launch_bounds__(256, 1) bgemm(
    const uint32_t* __restrict__ A, const uint32_t* __restrict__ B,
    float* __restrict__ C,
    int K, int lda, int ldb, int ldc,
    long long sA, long long sB, long long sC, float alpha)
{
    extern __shared__ uint32_t sm[];
    const uint32_t smb = smem_u32(sm);

    const int tid  = threadIdx.x;
    const int wid  = tid >> 5;
    const int lane = tid & 31;
    const int g    = lane >> 2;
    const int tg   = lane & 3;
    const int wm   = (wid >> 2) * 64;
    const int wn   = (wid & 3) * 32;

    const int z  = blockIdx.z;
    const int m0 = blockIdx.y * 128;
    const int n0 = blockIdx.x * 128;
    const uint32_t* Ag = A + (long long)z * sA + (long long)m0 * lda;
    const uint32_t* Bg = B + (long long)z * sB + (long long)n0 * ldb;
    C += (long long)z * sC;

    const int row_cp = tid >> 3;        // 0..31 (x4 iters -> 128 rows)
    const int cg_cp  = tid & 7;         // 16B granule in row

    const int nc = K >> 5;

    // issue stage c (copy A,B 128x32-word tiles into buf c%3)
    auto issue = [&](int c) {
        const int buf = c % NSTAGE;
        const uint32_t dA = smb + (uint32_t)buf * STAGE_WORDS * 4;
        const uint32_t dB = dA + TILE_WORDS * 4;
        const int k0 = c << 5;
#pragma unroll
        for (int i = 0; i < 4; i++) {
            const int row = row_cp + i * 32;
            cpa16(dA + (uint32_t)row * (TLW * 4) + cg_cp * 16,
                  Ag + (long long)row * lda + k0 + cg_cp * 4);
            cpa16(dB + (uint32_t)row * (TLW * 4) + cg_cp * 16,
                  Bg + (long long)row * ldb + k0 + cg_cp * 4);
        }
        cpa_commit();
    };

    float acc[4][4][4];
#pragma unroll
    for (int i = 0; i < 4; i++)
#pragma unroll
        for (int j = 0; j < 4; j++)
#pragma unroll
            for (int r = 0; r < 4; r++) acc[i][j][r] = 0.0f;

    issue(0);
    issue(1);

    for (int c = 0; c < nc; c++) {
        if (c + 1 < nc) asm volatile("cp.async.wait_group 1;");
        else            asm volatile("cp.async.wait_group 0;");
        __syncthreads();
        if (c + 2 < nc) issue(c + 2);

        const uint32_t* As = sm + (c % NSTAGE) * STAGE_WORDS;
        const uint32_t* Bs = As + TILE_WORDS;

#pragma unroll
        for (int ks = 0; ks < 2; ks++) {
            uint32_t ahi[4][4], alo[4][4], bhi[4][2], blo[4][2];
#pragma unroll
            for (int tm = 0; tm < 4; tm++) {
                const uint32_t* p = As + (wm + tm * 16 + g) * TLW + ks * 16 + 2 * tg;
                const uint2 w00 = *(const uint2*)p;
                const uint2 w01 = *(const uint2*)(p + 8);
                const uint2 w10 = *(const uint2*)(p + 8 * TLW);
                const uint2 w11 = *(const uint2*)(p + 8 * TLW + 8);
                ahi[tm][0] = __byte_perm(w00.x, w00.y, 0x7632);
                alo[tm][0] = __byte_perm(w00.x, w00.y, 0x5410);
                ahi[tm][1] = __byte_perm(w10.x, w10.y, 0x7632);
                alo[tm][1] = __byte_perm(w10.x, w10.y, 0x5410);
                ahi[tm][2] = __byte_perm(w01.x, w01.y, 0x7632);
                alo[tm][2] = __byte_perm(w01.x, w01.y, 0x5410);
                ahi[tm][3] = __byte_perm(w11.x, w11.y, 0x7632);
                alo[tm][3] = __byte_perm(w11.x, w11.y, 0x5410);
            }
#pragma unroll
            for (int tn = 0; tn < 4; tn++) {
                const uint32_t* p = Bs + (wn + tn * 8 + g) * TLW + ks * 16 + 2 * tg;
                const uint2 v0 = *(const uint2*)p;
                const uint2 v1 = *(const uint2*)(p + 8);
                bhi[tn][0] = __byte_perm(v0.x, v0.y, 0x7632);
                blo[tn][0] = __byte_perm(v0.x, v0.y, 0x5410);
                bhi[tn][1] = __byte_perm(v1.x, v1.y, 0x7632);
                blo[tn][1] = __byte_perm(v1.x, v1.y, 0x5410);
            }
            // pass 1: hi*hi
#pragma unroll
            for (int tm = 0; tm < 4; tm++)
#pragma unroll
                for (int tn = 0; tn < 4; tn++) MMA_BF16(acc[tm][tn], ahi[tm], bhi[tn]);
            // pass 2: hi*lo
#pragma unroll
            for (int tm = 0; tm < 4; tm++)
#pragma unroll
                for (int tn = 0; tn < 4; tn++) MMA_BF16(acc[tm][tn], ahi[tm], blo[tn]);
            // pass 3: lo*hi
#pragma unroll
            for (int tm = 0; tm < 4; tm++)
#pragma unroll
                for (int tn = 0; tn < 4; tn++) MMA_BF16(acc[tm][tn], alo[tm], bhi[tn]);
        }
        __syncthreads();
    }

    // epilogue
#pragma unroll
    for (int tm = 0; tm < 4; tm++) {
        const int row = m0 + wm + tm * 16 + g;
#pragma unroll
        for (int tn = 0; tn < 4; tn++) {
            const int col = n0 + wn + tn * 8 + 2 * tg;
            float2 lo, hi;
            lo.x = acc[tm][tn][0] * alpha; lo.y = acc[tm][tn][1] * alpha;
            hi.x = acc[tm][tn][2] * alpha; hi.y = acc[tm][tn][3] * alpha;
            *(float2*)(C + (long long)row * ldc + col) = lo;
            *(float2*)(C + (long long)(row + 8) * ldc + col) = hi;
        }
    }
}

// ---------------------------------------------------------------------------
// Elementwise fp32 -> packed bf16 hi/lo
// ---------------------------------------------------------------------------
__global__ void __launch_bounds__(256) pack_kernel(
    const float* __restrict__ in, uint32_t* __restrict__ out, long long n4)
{
    const long long i = (long long)blockIdx.x * 256 + threadIdx.x;
    if (i >= n4) return;
    const float4 v = ((const float4*)in)[i];
    uint4 o;
    o.x = pack_bf(v.x); o.y = pack_bf(v.y);
    o.z = pack_bf(v.z); o.w = pack_bf(v.w);
    ((uint4*)out)[i] = o;
}

// ---------------------------------------------------------------------------
// Transpose + pack: out[c][r] = pack(in[r][c]).  grid (C/32, R/32), 32x8.
// ---------------------------------------------------------------------------
__global__ void __launch_bounds__(256) transpose_pack_kernel(
    const float* __restrict__ in, uint32_t* __restrict__ out, int R, int C)
{
    __shared__ float tile[32][33];
    const int c0 = blockIdx.x * 32;
    const int r0 = blockIdx.y * 32;
    const int x = threadIdx.x;
    const int y = threadIdx.y;
#pragma unroll
    for (int i = 0; i < 32; i += 8)
        tile[y + i][x] = in[(long long)(r0 + y + i) * C + c0 + x];
    __syncthreads();
#pragma unroll
    for (int i = 0; i < 32; i += 8)
        out[(long long)(c0 + y + i) * R + r0 + x] = pack_bf(tile[x][y + i]);
}

// ---------------------------------------------------------------------------
// RoPE: read fp32 g_Q/g_K, write packed g_Qp/g_Kp.
// ---------------------------------------------------------------------------
__global__ void rope_pack_kernel(const int* __restrict__ pos_ids)
{
    const int s = blockIdx.x;
    const int j = threadIdx.x;           // 0..127
    const float p = (float)pos_ids[s];
    const float inv = expf(-((float)j * (1.0f / 128.0f)) * logf(10000.0f));
    const float ang = p * inv;
    const float c  = cosf(ang);
    const float sn = sinf(ang);

#pragma unroll
    for (int h = 0; h < NH; h++) {
        const float* q = g_Q + (size_t)s * HID + h * HD;
        uint32_t* qp = g_Qp + (size_t)s * HID + h * HD;
        const float x1 = q[j];
        const float x2 = q[j + 128];
        qp[j]       = pack_bf(x1 * c - x2 * sn);
        qp[j + 128] = pack_bf(x2 * c + x1 * sn);
    }
    const float* k = g_K + (size_t)s * HD;
    uint32_t* kp = g_Kp + (size_t)s * HD;
    const float x1 = k[j];
    const float x2 = k[j + 128];
    kp[j]       = pack_bf(x1 * c - x2 * sn);
    kp[j + 128] = pack_bf(x2 * c + x1 * sn);
}

// ---------------------------------------------------------------------------
// Softmax over g_S[h][q][:] + mask; writes packed bf16 hi/lo IN PLACE.
// ---------------------------------------------------------------------------
__global__ void __launch_bounds__(256) softmax_kernel(const float* __restrict__ mask)
{
    const int q = blockIdx.x;
    const int h = blockIdx.y;
    float* __restrict__ row = g_S + ((size_t)h * S_LEN + q) * S_LEN;
    const float* __restrict__ mrow = mask + (size_t)q * S_LEN;
    const int tid = threadIdx.x;

    float v[16];
    float m = -1e30f;
#pragma unroll
    for (int i = 0; i < 16; i++) {
        const int k = tid + i * 256;
        v[i] = row[k] + mrow[k];
        m = fmaxf(m, v[i]);
    }

    __shared__ float red[256];
    red[tid] = m;
    __syncthreads();
    for (int st = 128; st > 0; st >>= 1) {
        if (tid < st) red[tid] = fmaxf(red[tid], red[tid + st]);
        __syncthreads();
    }
    m = red[0];
    __syncthreads();

    float sum = 0.0f;
#pragma unroll
    for (int i = 0; i < 16; i++) {
        v[i] = __expf(v[i] - m);
        sum += v[i];
    }
    red[tid] = sum;
    __syncthreads();
    for (int st = 128; st > 0; st >>= 1) {
        if (tid < st) red[tid] += red[tid + st];
        __syncthreads();
    }
    const float inv = 1.0f / red[0];
    uint32_t* prow = (uint32_t*)row;
#pragma unroll
    for (int i = 0; i < 16; i++) prow[tid + i * 256] = pack_bf(v[i] * inv);
}

// ---------------------------------------------------------------------------
// Launch
// ---------------------------------------------------------------------------
extern "C" void kernel_launch(void* const* d_in, const int* in_sizes, int n_in,
                              void* d_out, int out_size)
{
    const float* X    = (const float*)d_in[0];
    const float* mask = (const float*)d_in[1];
    const int*   pos  = (const int*)d_in[2];
    const float* Wq   = (const float*)d_in[3];
    const float* Wk   = (const float*)d_in[4];
    const float* Wv   = (const float*)d_in[5];
    const float* Wo   = (const float*)d_in[6];
    float* out = (float*)d_out;

    float *Q, *K, *V, *Sb, *A;
    uint32_t *Xp, *Qp, *Kp, *VTp, *Ap, *WqTp, *WkTp, *WvTp, *WoTp;
    cudaGetSymbolAddress((void**)&Q,    g_Q);
    cudaGetSymbolAddress((void**)&K,    g_K);
    cudaGetSymbolAddress((void**)&V,    g_V);
    cudaGetSymbolAddress((void**)&Sb,   g_S);
    cudaGetSymbolAddress((void**)&A,    g_A);
    cudaGetSymbolAddress((void**)&Xp,   g_Xp);
    cudaGetSymbolAddress((void**)&Qp,   g_Qp);
    cudaGetSymbolAddress((void**)&Kp,   g_Kp);
    cudaGetSymbolAddress((void**)&VTp,  g_VTp);
    cudaGetSymbolAddress((void**)&Ap,   g_Ap);
    cudaGetSymbolAddress((void**)&WqTp, g_WqTp);
    cudaGetSymbolAddress((void**)&WkTp, g_WkTp);
    cudaGetSymbolAddress((void**)&WvTp, g_WvTp);
    cudaGetSymbolAddress((void**)&WoTp, g_WoTp);

    cudaFuncSetAttribute(bgemm, cudaFuncAttributeMaxDynamicSharedMemorySize, GEMM_SMEM);

    const dim3 tb(32, 8);

    // pack X; transpose+pack weights
    pack_kernel<<<(S_LEN * HID / 4 + 255) / 256, 256>>>(X, Xp, (long long)S_LEN * HID / 4);
    transpose_pack_kernel<<<dim3(HID / 32, HID / 32), tb>>>(Wq, WqTp, HID, HID);
    transpose_pack_kernel<<<dim3(HD  / 32, HID / 32), tb>>>(Wk, WkTp, HID, HD);
    transpose_pack_kernel<<<dim3(HD  / 32, HID / 32), tb>>>(Wv, WvTp, HID, HD);
    transpose_pack_kernel<<<dim3(HID / 32, HID / 32), tb>>>(Wo, WoTp, HID, HID);

    // projections (fp32 out)
    bgemm<<<dim3(HID / 128, S_LEN / 128, 1), 256, GEMM_SMEM>>>(
        Xp, WqTp, Q, HID, HID, HID, HID, 0, 0, 0, 1.0f);
    bgemm<<<dim3(HD / 128, S_LEN / 128, 1), 256, GEMM_SMEM>>>(
        Xp, WkTp, K, HID, HID, HID, HD, 0, 0, 0, 1.0f);
    bgemm<<<dim3(HD / 128, S_LEN / 128, 1), 256, GEMM_SMEM>>>(
        Xp, WvTp, V, HID, HID, HID, HD, 0, 0, 0, 1.0f);

    // RoPE -> packed Q/K ; V^T packed
    rope_pack_kernel<<<S_LEN, 128>>>(pos);
    transpose_pack_kernel<<<dim3(HD / 32, S_LEN / 32), tb>>>(V, VTp, S_LEN, HD);

    // scores[h] = (Q_h @ K^T)/16  (fp32)
    bgemm<<<dim3(S_LEN / 128, S_LEN / 128, NH), 256, GEMM_SMEM>>>(
        Qp, Kp, Sb, HD, HID, HD, S_LEN,
        (long long)HD, 0, (long long)S_LEN * S_LEN, 1.0f / 16.0f);

    // softmax -> packed P in place
    softmax_kernel<<<dim3(S_LEN, NH), 256>>>(mask);

    // A[:, h*256:] = P_h @ V  (A = packed scores, B = packed V^T)
    bgemm<<<dim3(HD / 128, S_LEN / 128, NH), 256, GEMM_SMEM>>>(
        (const uint32_t*)Sb, VTp, A, S_LEN, S_LEN, S_LEN, HID,
        (long long)S_LEN * S_LEN, 0, (long long)HD, 1.0f);

    // pack A ; out = A @ Wo
    pack_kernel<<<(S_LEN * HID / 4 + 255) / 256, 256>>>(A, Ap, (long long)S_LEN * HID / 4);
    bgemm<<<dim3(HID / 128, S_LEN / 128, 1), 256, GEMM_SMEM>>>(
        Ap, WoTp, out, HID, HID, HID, HID, 0, 0, 0, 1.0f);
}